// round 1
// baseline (speedup 1.0000x reference)
#include <cuda_runtime.h>
#include <math.h>

#define BB 4
#define LL 2048
#define DD 1024
#define HH 16
#define HDD 64

// Scratch (device globals — no allocations allowed)
__device__ float g_Q[BB*HH*LL*HDD];    // [b,h,l,hd]
__device__ float g_K[BB*HH*LL*HDD];
__device__ float g_V[BB*HH*LL*HDD];
__device__ float g_CTX[BB*LL*DD];      // [b,l,d]

// ---------------------------------------------------------------------------
// C = A[M,1024] @ W[1024,1024]^T   (both row-major, K contiguous -> TN GEMM)
// tile 64x64, BK=32, 256 threads, 4x4 micro-tile per thread.
// headmajor=1: write to [b,h,l,hd] layout (BN=64 == one head exactly).
// ---------------------------------------------------------------------------
__global__ __launch_bounds__(256) void gemm_tn(const float* __restrict__ A,
                                               const float* __restrict__ W,
                                               float* __restrict__ C,
                                               int headmajor)
{
    __shared__ float As[32][64];   // k-major
    __shared__ float Bs[32][64];
    const int tid = threadIdx.x;
    const int tx = tid & 15, ty = tid >> 4;
    const int m0 = blockIdx.y * 64;
    const int n0 = blockIdx.x * 64;

    float acc[4][4] = {};

    for (int k0 = 0; k0 < DD; k0 += 32) {
        #pragma unroll
        for (int it = 0; it < 2; it++) {
            int t2  = tid + it * 256;          // 512 float4s per operand tile
            int row = t2 >> 3;
            int c4  = (t2 & 7) << 2;
            float4 va = *(const float4*)&A[(size_t)(m0 + row) * DD + k0 + c4];
            As[c4+0][row] = va.x; As[c4+1][row] = va.y;
            As[c4+2][row] = va.z; As[c4+3][row] = va.w;
            float4 vb = *(const float4*)&W[(size_t)(n0 + row) * DD + k0 + c4];
            Bs[c4+0][row] = vb.x; Bs[c4+1][row] = vb.y;
            Bs[c4+2][row] = vb.z; Bs[c4+3][row] = vb.w;
        }
        __syncthreads();

        #pragma unroll
        for (int k = 0; k < 32; k++) {
            float4 a4 = *(const float4*)&As[k][ty << 2];
            float4 b4 = *(const float4*)&Bs[k][tx << 2];
            float av[4] = {a4.x, a4.y, a4.z, a4.w};
            float bv[4] = {b4.x, b4.y, b4.z, b4.w};
            #pragma unroll
            for (int i = 0; i < 4; i++)
                #pragma unroll
                for (int j = 0; j < 4; j++)
                    acc[i][j] += av[i] * bv[j];
        }
        __syncthreads();
    }

    if (headmajor) {
        int h = n0 >> 6;
        #pragma unroll
        for (int i = 0; i < 4; i++) {
            int m = m0 + (ty << 2) + i;
            int b = m >> 11, l = m & (LL - 1);
            float4 vv = make_float4(acc[i][0], acc[i][1], acc[i][2], acc[i][3]);
            *(float4*)&C[((size_t)((b * HH + h) * LL + l) << 6) + (tx << 2)] = vv;
        }
    } else {
        #pragma unroll
        for (int i = 0; i < 4; i++) {
            int m = m0 + (ty << 2) + i;
            float4 vv = make_float4(acc[i][0], acc[i][1], acc[i][2], acc[i][3]);
            *(float4*)&C[(size_t)m * DD + n0 + (tx << 2)] = vv;
        }
    }
}

// ---------------------------------------------------------------------------
// Per-head LayerNorm over HD=64, in place on [b,h,l,hd].
// One warp per row; 2 elems/lane.
// ---------------------------------------------------------------------------
__global__ __launch_bounds__(256) void ln_head(float* __restrict__ X,
                                               const float* __restrict__ gamma,
                                               const float* __restrict__ beta)
{
    int row  = blockIdx.x * 8 + (threadIdx.x >> 5);
    int lane = threadIdx.x & 31;
    float2 v = *(float2*)&X[(size_t)row * 64 + lane * 2];
    float s  = v.x + v.y;
    float sq = v.x * v.x + v.y * v.y;
    #pragma unroll
    for (int off = 16; off > 0; off >>= 1) {
        s  += __shfl_xor_sync(0xffffffffu, s,  off);
        sq += __shfl_xor_sync(0xffffffffu, sq, off);
    }
    float mean = s * (1.0f / 64.0f);
    float var  = sq * (1.0f / 64.0f) - mean * mean;
    float inv  = rsqrtf(var + 1e-5f);
    float g0 = gamma[lane * 2],     g1 = gamma[lane * 2 + 1];
    float b0 = beta[lane * 2],      b1 = beta[lane * 2 + 1];
    v.x = (v.x - mean) * inv * g0 + b0;
    v.y = (v.y - mean) * inv * g1 + b1;
    *(float2*)&X[(size_t)row * 64 + lane * 2] = v;
}

// ---------------------------------------------------------------------------
// Causal flash attention, fp32, BQ=BK=64, 256 threads, 4x4 micro-tiles.
// grid = (L/64, B*H). Skips fully-masked tiles (kt > qt).
// smem: Qs[d][q], Ks[d][k], Vs[k][d], Ps[k][q]  (4 x 16KB = 64KB dynamic)
// ---------------------------------------------------------------------------
__global__ __launch_bounds__(256) void flash_attn(const float* __restrict__ Q,
                                                  const float* __restrict__ K,
                                                  const float* __restrict__ V,
                                                  float* __restrict__ ctx)
{
    extern __shared__ float sm[];
    float* Qs = sm;           // [64][64] d-major: Qs[d*64+q]
    float* Ks = sm + 4096;    // Ks[d*64+k]
    float* Vs = sm + 8192;    // Vs[k*64+d]
    float* Ps = sm + 12288;   // Ps[k*64+q]

    const int tid = threadIdx.x;
    const int tx = tid & 15, ty = tid >> 4;
    const int qt = blockIdx.x;
    const int bh = blockIdx.y;

    const float* Qh = Q + (size_t)bh * LL * HDD;
    const float* Kh = K + (size_t)bh * LL * HDD;
    const float* Vh = V + (size_t)bh * LL * HDD;

    // Stage Q tile (transposed to d-major)
    #pragma unroll
    for (int it = 0; it < 4; it++) {
        int t2  = tid + it * 256;        // 1024 float4s
        int row = t2 >> 4;
        int c4  = (t2 & 15) << 2;
        float4 v = *(const float4*)&Qh[(size_t)(qt * 64 + row) * HDD + c4];
        Qs[(c4+0)*64 + row] = v.x; Qs[(c4+1)*64 + row] = v.y;
        Qs[(c4+2)*64 + row] = v.z; Qs[(c4+3)*64 + row] = v.w;
    }

    float o[4][4] = {};
    float mi[4] = {-INFINITY, -INFINITY, -INFINITY, -INFINITY};
    float li[4] = {};

    for (int kt = 0; kt <= qt; kt++) {
        // load K (transposed) and V tiles
        #pragma unroll
        for (int it = 0; it < 4; it++) {
            int t2  = tid + it * 256;
            int row = t2 >> 4;
            int c4  = (t2 & 15) << 2;
            float4 v = *(const float4*)&Kh[(size_t)(kt * 64 + row) * HDD + c4];
            Ks[(c4+0)*64 + row] = v.x; Ks[(c4+1)*64 + row] = v.y;
            Ks[(c4+2)*64 + row] = v.z; Ks[(c4+3)*64 + row] = v.w;
            float4 w = *(const float4*)&Vh[(size_t)(kt * 64 + row) * HDD + c4];
            *(float4*)&Vs[row * 64 + c4] = w;
        }
        __syncthreads();

        // S = Q @ K^T
        float s[4][4] = {};
        #pragma unroll
        for (int d = 0; d < 64; d++) {
            float4 a4 = *(const float4*)&Qs[d * 64 + (ty << 2)];
            float4 b4 = *(const float4*)&Ks[d * 64 + (tx << 2)];
            float av[4] = {a4.x, a4.y, a4.z, a4.w};
            float bv[4] = {b4.x, b4.y, b4.z, b4.w};
            #pragma unroll
            for (int i = 0; i < 4; i++)
                #pragma unroll
                for (int j = 0; j < 4; j++)
                    s[i][j] += av[i] * bv[j];
        }

        // scale + causal mask (only diagonal tile needs masking)
        #pragma unroll
        for (int i = 0; i < 4; i++)
            #pragma unroll
            for (int j = 0; j < 4; j++)
                s[i][j] *= 0.125f;
        if (kt == qt) {
            #pragma unroll
            for (int i = 0; i < 4; i++)
                #pragma unroll
                for (int j = 0; j < 4; j++)
                    if ((tx << 2) + j > (ty << 2) + i) s[i][j] = -1e30f;
        }

        // online softmax (row group = 16 lanes sharing ty)
        #pragma unroll
        for (int i = 0; i < 4; i++) {
            float rm = fmaxf(fmaxf(s[i][0], s[i][1]), fmaxf(s[i][2], s[i][3]));
            #pragma unroll
            for (int off = 8; off > 0; off >>= 1)
                rm = fmaxf(rm, __shfl_xor_sync(0xffffffffu, rm, off));
            float mnew = fmaxf(mi[i], rm);
            float fac  = __expf(mi[i] - mnew);
            float rs = 0.0f;
            #pragma unroll
            for (int j = 0; j < 4; j++) {
                s[i][j] = __expf(s[i][j] - mnew);
                rs += s[i][j];
            }
            #pragma unroll
            for (int off = 8; off > 0; off >>= 1)
                rs += __shfl_xor_sync(0xffffffffu, rs, off);
            li[i] = li[i] * fac + rs;
            mi[i] = mnew;
            #pragma unroll
            for (int j = 0; j < 4; j++) o[i][j] *= fac;
        }

        // stage P (k-major)
        #pragma unroll
        for (int i = 0; i < 4; i++)
            #pragma unroll
            for (int j = 0; j < 4; j++)
                Ps[((tx << 2) + j) * 64 + (ty << 2) + i] = s[i][j];
        __syncthreads();

        // O += P @ V
        #pragma unroll
        for (int k = 0; k < 64; k++) {
            float4 p4 = *(const float4*)&Ps[k * 64 + (ty << 2)];
            float4 v4 = *(const float4*)&Vs[k * 64 + (tx << 2)];
            float pv[4] = {p4.x, p4.y, p4.z, p4.w};
            float vv[4] = {v4.x, v4.y, v4.z, v4.w};
            #pragma unroll
            for (int i = 0; i < 4; i++)
                #pragma unroll
                for (int j = 0; j < 4; j++)
                    o[i][j] += pv[i] * vv[j];
        }
        __syncthreads();
    }

    // epilogue: normalize, write to ctx in [b,l,d] layout
    int b = bh >> 4, h = bh & 15;
    #pragma unroll
    for (int i = 0; i < 4; i++) {
        float inv = 1.0f / li[i];
        int qg = qt * 64 + (ty << 2) + i;
        float4 vv = make_float4(o[i][0] * inv, o[i][1] * inv,
                                o[i][2] * inv, o[i][3] * inv);
        *(float4*)&ctx[(size_t)(b * LL + qg) * DD + h * 64 + (tx << 2)] = vv;
    }
}

// ---------------------------------------------------------------------------
extern "C" void kernel_launch(void* const* d_in, const int* in_sizes, int n_in,
                              void* d_out, int out_size)
{
    const float* x      = (const float*)d_in[0];
    // d_in[1] = causal mask (tril) — causality applied analytically, unused
    const float* Wq     = (const float*)d_in[2];
    const float* Wk     = (const float*)d_in[3];
    const float* Wv     = (const float*)d_in[4];
    const float* Wo     = (const float*)d_in[5];
    const float* qgamma = (const float*)d_in[6];
    const float* qbeta  = (const float*)d_in[7];
    const float* kgamma = (const float*)d_in[8];
    const float* kbeta  = (const float*)d_in[9];
    float* out = (float*)d_out;

    float *dQ, *dK, *dV, *dC;
    cudaGetSymbolAddress((void**)&dQ, g_Q);
    cudaGetSymbolAddress((void**)&dK, g_K);
    cudaGetSymbolAddress((void**)&dV, g_V);
    cudaGetSymbolAddress((void**)&dC, g_CTX);

    cudaFuncSetAttribute(flash_attn,
                         cudaFuncAttributeMaxDynamicSharedMemorySize, 65536);

    dim3 gg(DD / 64, (BB * LL) / 64);   // (16, 128)

    gemm_tn<<<gg, 256>>>(x, Wq, dQ, 1);
    gemm_tn<<<gg, 256>>>(x, Wk, dK, 1);
    gemm_tn<<<gg, 256>>>(x, Wv, dV, 1);

    ln_head<<<(BB * HH * LL) / 8, 256>>>(dQ, qgamma, qbeta);
    ln_head<<<(BB * HH * LL) / 8, 256>>>(dK, kgamma, kbeta);

    flash_attn<<<dim3(LL / 64, BB * HH), 256, 65536>>>(dQ, dK, dV, dC);

    gemm_tn<<<gg, 256>>>(dC, Wo, out, 0);
}

// round 4
// speedup vs baseline: 1.7792x; 1.7792x over previous
#include <cuda_runtime.h>
#include <cuda_bf16.h>
#include <math.h>
#include <stdint.h>

#define BB 4
#define LL 2048
#define DD 1024
#define HH 16
#define HDD 64

// Scratch (device globals — no allocations allowed)
__device__ float g_Q[BB*HH*LL*HDD];    // [b,h,l,hd]
__device__ float g_K[BB*HH*LL*HDD];
__device__ float g_V[BB*HH*LL*HDD];
__device__ float g_CTX[BB*LL*DD];      // [b,l,d]

// ===========================================================================
// helpers
// ===========================================================================
__device__ __forceinline__ uint32_t smem_u32(const void* p) {
    uint32_t a;
    asm("{ .reg .u64 t; cvta.to.shared.u64 t, %1; cvt.u32.u64 %0, t; }"
        : "=r"(a) : "l"(p));
    return a;
}

__device__ __forceinline__ uint32_t lds32(uint32_t addr) {
    uint32_t v;
    asm volatile("ld.shared.b32 %0, [%1];" : "=r"(v) : "r"(addr));
    return v;
}

__device__ __forceinline__ void sts64(uint32_t addr, uint32_t a, uint32_t b) {
    asm volatile("st.shared.v2.b32 [%0], {%1, %2};" :: "r"(addr), "r"(a), "r"(b));
}

__device__ __forceinline__ void mma_bf16(float* c, const uint32_t* a, const uint32_t* b) {
    asm volatile(
        "mma.sync.aligned.m16n8k16.row.col.f32.bf16.bf16.f32 "
        "{%0,%1,%2,%3}, {%4,%5,%6,%7}, {%8,%9}, {%0,%1,%2,%3};"
        : "+f"(c[0]), "+f"(c[1]), "+f"(c[2]), "+f"(c[3])
        : "r"(a[0]), "r"(a[1]), "r"(a[2]), "r"(a[3]), "r"(b[0]), "r"(b[1]));
}

// split two floats into packed bf16 hi + bf16 lo (residual)
__device__ __forceinline__ void split2(float a, float b, uint32_t& h, uint32_t& l) {
    __nv_bfloat16 ha = __float2bfloat16_rn(a);
    __nv_bfloat16 hb = __float2bfloat16_rn(b);
    float ra = a - __bfloat162float(ha);
    float rb = b - __bfloat162float(hb);
    __nv_bfloat162 hv; hv.x = ha; hv.y = hb;
    __nv_bfloat162 lv = __floats2bfloat162_rn(ra, rb);
    h = *(uint32_t*)&hv;
    l = *(uint32_t*)&lv;
}

// ===========================================================================
// bf16x3 mma.sync GEMM: C[M,1024] = A[M,1024] @ W[1024,1024]^T
// CTA tile 128x128, BK=32, 8 warps (2m x 4n), warp tile 64x32.
// SMEM: per buffer {Ahi, Alo, Bhi, Blo} each 128x32 bf16 (8KB), 2 buffers.
// Swizzle: 16B chunk index ^= (row>>1)&3  -> conflict-free fragment loads.
// ===========================================================================
#define SM_AHI 0
#define SM_ALO 8192
#define SM_BHI 16384
#define SM_BLO 24576
#define SM_BUF 32768

__device__ __forceinline__ uint32_t sw_sts(uint32_t base, int row, int col4) {
    return base + row * 64 + ((((col4 >> 1) ^ ((row >> 1) & 3)) << 4)) + ((col4 & 1) << 3);
}
__device__ __forceinline__ uint32_t sw_lds(uint32_t base, int row, int chunk, int lane) {
    return base + row * 64 + (((chunk ^ ((row >> 1) & 3)) << 4)) + ((lane & 3) << 2);
}

__global__ __launch_bounds__(256) void gemm_mma(const float* __restrict__ A,
                                                const float* __restrict__ W,
                                                float* __restrict__ C,
                                                int headmajor)
{
    extern __shared__ char gsm[];
    const uint32_t smb = smem_u32(gsm);
    const int tid  = threadIdx.x;
    const int lane = tid & 31;
    const int wid  = tid >> 5;
    const int wm0  = (wid & 1) * 64;    // 2 warps along M
    const int wn0  = (wid >> 1) * 32;   // 4 warps along N
    const int m0   = blockIdx.y * 128;
    const int n0   = blockIdx.x * 128;

    float acc[4][4][4] = {};            // [mt][nt][frag]

    // per-thread load coords (4 float4 per operand per K-step)
    int lrow[4], lc4[4];
    #pragma unroll
    for (int i = 0; i < 4; i++) {
        int idx = tid + i * 256;
        lrow[i] = idx >> 3;
        lc4[i]  = idx & 7;
    }

    float4 pa[4], pb[4];
    #pragma unroll
    for (int i = 0; i < 4; i++) {
        pa[i] = *(const float4*)&A[(size_t)(m0 + lrow[i]) * DD + lc4[i] * 4];
        pb[i] = *(const float4*)&W[(size_t)(n0 + lrow[i]) * DD + lc4[i] * 4];
    }

    // STS of prefetched regs into buffer `buf`
    auto do_sts = [&](int buf) {
        uint32_t b = smb + buf * SM_BUF;
        #pragma unroll
        for (int i = 0; i < 4; i++) {
            uint32_t h0, l0, h1, l1;
            split2(pa[i].x, pa[i].y, h0, l0);
            split2(pa[i].z, pa[i].w, h1, l1);
            uint32_t ad = sw_sts(b + SM_AHI, lrow[i], lc4[i]);
            sts64(ad, h0, h1);
            sts64(ad + (SM_ALO - SM_AHI), l0, l1);
            split2(pb[i].x, pb[i].y, h0, l0);
            split2(pb[i].z, pb[i].w, h1, l1);
            uint32_t bd = sw_sts(b + SM_BHI, lrow[i], lc4[i]);
            sts64(bd, h0, h1);
            sts64(bd + (SM_BLO - SM_BHI), l0, l1);
        }
    };

    do_sts(0);
    __syncthreads();

    for (int kb = 0; kb < 32; kb++) {
        const int buf = kb & 1;
        if (kb + 1 < 32) {
            const int k0 = (kb + 1) * 32;
            #pragma unroll
            for (int i = 0; i < 4; i++) {
                pa[i] = *(const float4*)&A[(size_t)(m0 + lrow[i]) * DD + k0 + lc4[i] * 4];
                pb[i] = *(const float4*)&W[(size_t)(n0 + lrow[i]) * DD + k0 + lc4[i] * 4];
            }
        }

        const uint32_t bb = smb + buf * SM_BUF;
        #pragma unroll
        for (int ks = 0; ks < 2; ks++) {
            uint32_t aH[4][4], aL[4][4];
            #pragma unroll
            for (int mt = 0; mt < 4; mt++) {
                int r = wm0 + mt * 16 + (lane >> 2);
                aH[mt][0] = lds32(sw_lds(bb + SM_AHI, r,     2*ks,   lane));
                aH[mt][1] = lds32(sw_lds(bb + SM_AHI, r + 8, 2*ks,   lane));
                aH[mt][2] = lds32(sw_lds(bb + SM_AHI, r,     2*ks+1, lane));
                aH[mt][3] = lds32(sw_lds(bb + SM_AHI, r + 8, 2*ks+1, lane));
                aL[mt][0] = lds32(sw_lds(bb + SM_ALO, r,     2*ks,   lane));
                aL[mt][1] = lds32(sw_lds(bb + SM_ALO, r + 8, 2*ks,   lane));
                aL[mt][2] = lds32(sw_lds(bb + SM_ALO, r,     2*ks+1, lane));
                aL[mt][3] = lds32(sw_lds(bb + SM_ALO, r + 8, 2*ks+1, lane));
            }
            uint32_t bH[4][2], bL[4][2];
            #pragma unroll
            for (int nt = 0; nt < 4; nt++) {
                int rn = wn0 + nt * 8 + (lane >> 2);
                bH[nt][0] = lds32(sw_lds(bb + SM_BHI, rn, 2*ks,   lane));
                bH[nt][1] = lds32(sw_lds(bb + SM_BHI, rn, 2*ks+1, lane));
                bL[nt][0] = lds32(sw_lds(bb + SM_BLO, rn, 2*ks,   lane));
                bL[nt][1] = lds32(sw_lds(bb + SM_BLO, rn, 2*ks+1, lane));
            }
            #pragma unroll
            for (int mt = 0; mt < 4; mt++)
                #pragma unroll
                for (int nt = 0; nt < 4; nt++) {
                    mma_bf16(acc[mt][nt], aH[mt], bH[nt]);
                    mma_bf16(acc[mt][nt], aH[mt], bL[nt]);
                    mma_bf16(acc[mt][nt], aL[mt], bH[nt]);
                }
        }

        if (kb + 1 < 32) {
            do_sts(buf ^ 1);
            __syncthreads();
        }
    }

    // epilogue
    #pragma unroll
    for (int mt = 0; mt < 4; mt++) {
        #pragma unroll
        for (int nt = 0; nt < 4; nt++) {
            int row = m0 + wm0 + mt * 16 + (lane >> 2);
            int col = n0 + wn0 + nt * 8 + ((lane & 3) << 1);
            #pragma unroll
            for (int h = 0; h < 2; h++) {
                int r = row + h * 8;
                float2 v = make_float2(acc[mt][nt][2*h], acc[mt][nt][2*h + 1]);
                if (headmajor) {
                    int bI = r >> 11, l = r & (LL - 1);
                    int hh = col >> 6, hd = col & 63;
                    *(float2*)&C[((size_t)((bI * HH + hh) * LL + l) << 6) + hd] = v;
                } else {
                    *(float2*)&C[(size_t)r * DD + col] = v;
                }
            }
        }
    }
}

// ---------------------------------------------------------------------------
// Per-head LayerNorm over HD=64, in place on [b,h,l,hd].
// ---------------------------------------------------------------------------
__global__ __launch_bounds__(256) void ln_head(float* __restrict__ X,
                                               const float* __restrict__ gamma,
                                               const float* __restrict__ beta)
{
    int row  = blockIdx.x * 8 + (threadIdx.x >> 5);
    int lane = threadIdx.x & 31;
    float2 v = *(float2*)&X[(size_t)row * 64 + lane * 2];
    float s  = v.x + v.y;
    float sq = v.x * v.x + v.y * v.y;
    #pragma unroll
    for (int off = 16; off > 0; off >>= 1) {
        s  += __shfl_xor_sync(0xffffffffu, s,  off);
        sq += __shfl_xor_sync(0xffffffffu, sq, off);
    }
    float mean = s * (1.0f / 64.0f);
    float var  = sq * (1.0f / 64.0f) - mean * mean;
    float inv  = rsqrtf(var + 1e-5f);
    float g0 = gamma[lane * 2],     g1 = gamma[lane * 2 + 1];
    float b0 = beta[lane * 2],      b1 = beta[lane * 2 + 1];
    v.x = (v.x - mean) * inv * g0 + b0;
    v.y = (v.y - mean) * inv * g1 + b1;
    *(float2*)&X[(size_t)row * 64 + lane * 2] = v;
}

// ---------------------------------------------------------------------------
// Causal flash attention, fp32, BQ=BK=64, 256 threads, 4x4 micro-tiles.
// ---------------------------------------------------------------------------
__global__ __launch_bounds__(256) void flash_attn(const float* __restrict__ Q,
                                                  const float* __restrict__ K,
                                                  const float* __restrict__ V,
                                                  float* __restrict__ ctx)
{
    extern __shared__ float fsm[];
    float* Qs = fsm;           // Qs[d*64+q]
    float* Ks = fsm + 4096;    // Ks[d*64+k]
    float* Vs = fsm + 8192;    // Vs[k*64+d]
    float* Ps = fsm + 12288;   // Ps[k*64+q]

    const int tid = threadIdx.x;
    const int tx = tid & 15, ty = tid >> 4;
    const int qt = blockIdx.x;
    const int bh = blockIdx.y;

    const float* Qh = Q + (size_t)bh * LL * HDD;
    const float* Kh = K + (size_t)bh * LL * HDD;
    const float* Vh = V + (size_t)bh * LL * HDD;

    #pragma unroll
    for (int it = 0; it < 4; it++) {
        int t2  = tid + it * 256;
        int row = t2 >> 4;
        int c4  = (t2 & 15) << 2;
        float4 v = *(const float4*)&Qh[(size_t)(qt * 64 + row) * HDD + c4];
        Qs[(c4+0)*64 + row] = v.x; Qs[(c4+1)*64 + row] = v.y;
        Qs[(c4+2)*64 + row] = v.z; Qs[(c4+3)*64 + row] = v.w;
    }

    float o[4][4] = {};
    float mi[4] = {-INFINITY, -INFINITY, -INFINITY, -INFINITY};
    float li[4] = {};

    for (int kt = 0; kt <= qt; kt++) {
        #pragma unroll
        for (int it = 0; it < 4; it++) {
            int t2  = tid + it * 256;
            int row = t2 >> 4;
            int c4  = (t2 & 15) << 2;
            float4 v = *(const float4*)&Kh[(size_t)(kt * 64 + row) * HDD + c4];
            Ks[(c4+0)*64 + row] = v.x; Ks[(c4+1)*64 + row] = v.y;
            Ks[(c4+2)*64 + row] = v.z; Ks[(c4+3)*64 + row] = v.w;
            float4 w = *(const float4*)&Vh[(size_t)(kt * 64 + row) * HDD + c4];
            *(float4*)&Vs[row * 64 + c4] = w;
        }
        __syncthreads();

        float s[4][4] = {};
        #pragma unroll
        for (int d = 0; d < 64; d++) {
            float4 a4 = *(const float4*)&Qs[d * 64 + (ty << 2)];
            float4 b4 = *(const float4*)&Ks[d * 64 + (tx << 2)];
            float av[4] = {a4.x, a4.y, a4.z, a4.w};
            float bv[4] = {b4.x, b4.y, b4.z, b4.w};
            #pragma unroll
            for (int i = 0; i < 4; i++)
                #pragma unroll
                for (int j = 0; j < 4; j++)
                    s[i][j] += av[i] * bv[j];
        }

        #pragma unroll
        for (int i = 0; i < 4; i++)
            #pragma unroll
            for (int j = 0; j < 4; j++)
                s[i][j] *= 0.125f;
        if (kt == qt) {
            #pragma unroll
            for (int i = 0; i < 4; i++)
                #pragma unroll
                for (int j = 0; j < 4; j++)
                    if ((tx << 2) + j > (ty << 2) + i) s[i][j] = -1e30f;
        }

        #pragma unroll
        for (int i = 0; i < 4; i++) {
            float rm = fmaxf(fmaxf(s[i][0], s[i][1]), fmaxf(s[i][2], s[i][3]));
            #pragma unroll
            for (int off = 8; off > 0; off >>= 1)
                rm = fmaxf(rm, __shfl_xor_sync(0xffffffffu, rm, off));
            float mnew = fmaxf(mi[i], rm);
            float fac  = __expf(mi[i] - mnew);
            float rs = 0.0f;
            #pragma unroll
            for (int j = 0; j < 4; j++) {
                s[i][j] = __expf(s[i][j] - mnew);
                rs += s[i][j];
            }
            #pragma unroll
            for (int off = 8; off > 0; off >>= 1)
                rs += __shfl_xor_sync(0xffffffffu, rs, off);
            li[i] = li[i] * fac + rs;
            mi[i] = mnew;
            #pragma unroll
            for (int j = 0; j < 4; j++) o[i][j] *= fac;
        }

        #pragma unroll
        for (int i = 0; i < 4; i++)
            #pragma unroll
            for (int j = 0; j < 4; j++)
                Ps[((tx << 2) + j) * 64 + (ty << 2) + i] = s[i][j];
        __syncthreads();

        #pragma unroll
        for (int k = 0; k < 64; k++) {
            float4 p4 = *(const float4*)&Ps[k * 64 + (ty << 2)];
            float4 v4 = *(const float4*)&Vs[k * 64 + (tx << 2)];
            float pv[4] = {p4.x, p4.y, p4.z, p4.w};
            float vv[4] = {v4.x, v4.y, v4.z, v4.w};
            #pragma unroll
            for (int i = 0; i < 4; i++)
                #pragma unroll
                for (int j = 0; j < 4; j++)
                    o[i][j] += pv[i] * vv[j];
        }
        __syncthreads();
    }

    int b = bh >> 4, h = bh & 15;
    #pragma unroll
    for (int i = 0; i < 4; i++) {
        float inv = 1.0f / li[i];
        int qg = qt * 64 + (ty << 2) + i;
        float4 vv = make_float4(o[i][0] * inv, o[i][1] * inv,
                                o[i][2] * inv, o[i][3] * inv);
        *(float4*)&ctx[(size_t)(b * LL + qg) * DD + h * 64 + (tx << 2)] = vv;
    }
}

// ---------------------------------------------------------------------------
extern "C" void kernel_launch(void* const* d_in, const int* in_sizes, int n_in,
                              void* d_out, int out_size)
{
    const float* x      = (const float*)d_in[0];
    // d_in[1] = causal mask (tril) — causality applied analytically, unused
    const float* Wq     = (const float*)d_in[2];
    const float* Wk     = (const float*)d_in[3];
    const float* Wv     = (const float*)d_in[4];
    const float* Wo     = (const float*)d_in[5];
    const float* qgamma = (const float*)d_in[6];
    const float* qbeta  = (const float*)d_in[7];
    const float* kgamma = (const float*)d_in[8];
    const float* kbeta  = (const float*)d_in[9];
    float* out = (float*)d_out;

    float *dQ, *dK, *dV, *dC;
    cudaGetSymbolAddress((void**)&dQ, g_Q);
    cudaGetSymbolAddress((void**)&dK, g_K);
    cudaGetSymbolAddress((void**)&dV, g_V);
    cudaGetSymbolAddress((void**)&dC, g_CTX);

    const int gemm_smem = 2 * SM_BUF;   // 64 KB
    cudaFuncSetAttribute(gemm_mma,
                         cudaFuncAttributeMaxDynamicSharedMemorySize, gemm_smem);
    cudaFuncSetAttribute(flash_attn,
                         cudaFuncAttributeMaxDynamicSharedMemorySize, 65536);

    dim3 gg(DD / 128, (BB * LL) / 128);   // (8, 64)

    gemm_mma<<<gg, 256, gemm_smem>>>(x, Wq, dQ, 1);
    gemm_mma<<<gg, 256, gemm_smem>>>(x, Wk, dK, 1);
    gemm_mma<<<gg, 256, gemm_smem>>>(x, Wv, dV, 1);

    ln_head<<<(BB * HH * LL) / 8, 256>>>(dQ, qgamma, qbeta);
    ln_head<<<(BB * HH * LL) / 8, 256>>>(dK, kgamma, kbeta);

    flash_attn<<<dim3(LL / 64, BB * HH), 256, 65536>>>(dQ, dK, dV, dC);

    gemm_mma<<<gg, 256, gemm_smem>>>(dC, Wo, out, 0);
}

// round 5
// speedup vs baseline: 3.5072x; 1.9712x over previous
#include <cuda_runtime.h>
#include <cuda_bf16.h>
#include <math.h>
#include <stdint.h>

#define BB 4
#define LL 2048
#define DD 1024
#define HH 16
#define HDD 64

// Scratch (device globals — no allocations allowed)
__device__ float g_Q[BB*HH*LL*HDD];    // [b,h,l,hd] fp32 (LN'd in place)
__device__ float g_K[BB*HH*LL*HDD];    // [b,h,l,hd] fp32 pre-LN
__device__ float g_CTX[BB*LL*DD];      // [b,l,d]
__device__ __nv_bfloat16 g_Kh[BB*HH*LL*HDD];
__device__ __nv_bfloat16 g_Kl[BB*HH*LL*HDD];
__device__ __nv_bfloat16 g_Vh[BB*HH*LL*HDD];
__device__ __nv_bfloat16 g_Vl[BB*HH*LL*HDD];

// ===========================================================================
// helpers
// ===========================================================================
__device__ __forceinline__ uint32_t smem_u32(const void* p) {
    uint32_t a;
    asm("{ .reg .u64 t; cvta.to.shared.u64 t, %1; cvt.u32.u64 %0, t; }"
        : "=r"(a) : "l"(p));
    return a;
}

__device__ __forceinline__ uint32_t lds32(uint32_t addr) {
    uint32_t v;
    asm volatile("ld.shared.b32 %0, [%1];" : "=r"(v) : "r"(addr));
    return v;
}

__device__ __forceinline__ void sts64(uint32_t addr, uint32_t a, uint32_t b) {
    asm volatile("st.shared.v2.b32 [%0], {%1, %2};" :: "r"(addr), "r"(a), "r"(b));
}

__device__ __forceinline__ void mma_bf16(float* c, const uint32_t* a, const uint32_t* b) {
    asm volatile(
        "mma.sync.aligned.m16n8k16.row.col.f32.bf16.bf16.f32 "
        "{%0,%1,%2,%3}, {%4,%5,%6,%7}, {%8,%9}, {%0,%1,%2,%3};"
        : "+f"(c[0]), "+f"(c[1]), "+f"(c[2]), "+f"(c[3])
        : "r"(a[0]), "r"(a[1]), "r"(a[2]), "r"(a[3]), "r"(b[0]), "r"(b[1]));
}

__device__ __forceinline__ void ldmx4(uint32_t* r, uint32_t addr) {
    asm volatile("ldmatrix.sync.aligned.m8n8.x4.shared.b16 {%0,%1,%2,%3}, [%4];"
                 : "=r"(r[0]), "=r"(r[1]), "=r"(r[2]), "=r"(r[3]) : "r"(addr));
}
__device__ __forceinline__ void ldmx4t(uint32_t* r, uint32_t addr) {
    asm volatile("ldmatrix.sync.aligned.m8n8.x4.trans.shared.b16 {%0,%1,%2,%3}, [%4];"
                 : "=r"(r[0]), "=r"(r[1]), "=r"(r[2]), "=r"(r[3]) : "r"(addr));
}

__device__ __forceinline__ void cp16(uint32_t dst, const void* src) {
    asm volatile("cp.async.cg.shared.global [%0], [%1], 16;" :: "r"(dst), "l"(src));
}
#define CP_COMMIT() asm volatile("cp.async.commit_group;" ::: "memory")
#define CP_WAIT1()  asm volatile("cp.async.wait_group 1;" ::: "memory")

// split two floats into packed bf16 hi + bf16 lo (residual). low half = first.
__device__ __forceinline__ void split2(float a, float b, uint32_t& h, uint32_t& l) {
    __nv_bfloat16 ha = __float2bfloat16_rn(a);
    __nv_bfloat16 hb = __float2bfloat16_rn(b);
    float ra = a - __bfloat162float(ha);
    float rb = b - __bfloat162float(hb);
    __nv_bfloat162 hv; hv.x = ha; hv.y = hb;
    __nv_bfloat162 lv = __floats2bfloat162_rn(ra, rb);
    h = *(uint32_t*)&hv;
    l = *(uint32_t*)&lv;
}

// pack two floats to bf16x2: lo -> low half, hi -> high half
__device__ __forceinline__ uint32_t pack_bf16(float lo, float hi) {
    uint32_t r;
    asm("cvt.rn.bf16x2.f32 %0, %1, %2;" : "=r"(r) : "f"(hi), "f"(lo));
    return r;
}

// fast 2^t on FMA/ALU pipes (no MUFU). t <= 0 expected; clamped at -100.
__device__ __forceinline__ float exp2p(float t) {
    t = fmaxf(t, -100.0f);
    float z = t + 12582912.0f;            // round-to-nearest-int via magic
    float f = t - (z - 12582912.0f);      // f in [-0.5, 0.5]
    float p =             1.3333558e-3f;
    p = fmaf(p, f, 9.6181291e-3f);
    p = fmaf(p, f, 5.5504109e-2f);
    p = fmaf(p, f, 2.4022651e-1f);
    p = fmaf(p, f, 6.9314718e-1f);
    p = fmaf(p, f, 1.0f);
    return __int_as_float(__float_as_int(p) + (__float_as_int(z) << 23));
}

// ===========================================================================
// bf16x3 mma.sync GEMM: C[M,1024] = A[M,1024] @ W[1024,1024]^T
// mode 0: fp32 row-major out; 1: fp32 head-major; 2: bf16 hi/lo head-major
// ===========================================================================
#define SM_AHI 0
#define SM_ALO 8192
#define SM_BHI 16384
#define SM_BLO 24576
#define SM_BUF 32768

__device__ __forceinline__ uint32_t sw_sts(uint32_t base, int row, int col4) {
    return base + row * 64 + ((((col4 >> 1) ^ ((row >> 1) & 3)) << 4)) + ((col4 & 1) << 3);
}
__device__ __forceinline__ uint32_t sw_lds(uint32_t base, int row, int chunk, int lane) {
    return base + row * 64 + (((chunk ^ ((row >> 1) & 3)) << 4)) + ((lane & 3) << 2);
}

__global__ __launch_bounds__(256) void gemm_mma(const float* __restrict__ A,
                                                const float* __restrict__ W,
                                                float* __restrict__ C,
                                                __nv_bfloat16* __restrict__ Ch,
                                                __nv_bfloat16* __restrict__ Cl,
                                                int mode)
{
    extern __shared__ char gsm[];
    const uint32_t smb = smem_u32(gsm);
    const int tid  = threadIdx.x;
    const int lane = tid & 31;
    const int wid  = tid >> 5;
    const int wm0  = (wid & 1) * 64;
    const int wn0  = (wid >> 1) * 32;
    const int m0   = blockIdx.y * 128;
    const int n0   = blockIdx.x * 128;

    float acc[4][4][4] = {};

    int lrow[4], lc4[4];
    #pragma unroll
    for (int i = 0; i < 4; i++) {
        int idx = tid + i * 256;
        lrow[i] = idx >> 3;
        lc4[i]  = idx & 7;
    }

    float4 pa[4], pb[4];
    #pragma unroll
    for (int i = 0; i < 4; i++) {
        pa[i] = *(const float4*)&A[(size_t)(m0 + lrow[i]) * DD + lc4[i] * 4];
        pb[i] = *(const float4*)&W[(size_t)(n0 + lrow[i]) * DD + lc4[i] * 4];
    }

    auto do_sts = [&](int buf) {
        uint32_t b = smb + buf * SM_BUF;
        #pragma unroll
        for (int i = 0; i < 4; i++) {
            uint32_t h0, l0, h1, l1;
            split2(pa[i].x, pa[i].y, h0, l0);
            split2(pa[i].z, pa[i].w, h1, l1);
            uint32_t ad = sw_sts(b + SM_AHI, lrow[i], lc4[i]);
            sts64(ad, h0, h1);
            sts64(ad + (SM_ALO - SM_AHI), l0, l1);
            split2(pb[i].x, pb[i].y, h0, l0);
            split2(pb[i].z, pb[i].w, h1, l1);
            uint32_t bd = sw_sts(b + SM_BHI, lrow[i], lc4[i]);
            sts64(bd, h0, h1);
            sts64(bd + (SM_BLO - SM_BHI), l0, l1);
        }
    };

    do_sts(0);
    __syncthreads();

    for (int kb = 0; kb < 32; kb++) {
        const int buf = kb & 1;
        if (kb + 1 < 32) {
            const int k0 = (kb + 1) * 32;
            #pragma unroll
            for (int i = 0; i < 4; i++) {
                pa[i] = *(const float4*)&A[(size_t)(m0 + lrow[i]) * DD + k0 + lc4[i] * 4];
                pb[i] = *(const float4*)&W[(size_t)(n0 + lrow[i]) * DD + k0 + lc4[i] * 4];
            }
        }

        const uint32_t bb = smb + buf * SM_BUF;
        #pragma unroll
        for (int ks = 0; ks < 2; ks++) {
            uint32_t aH[4][4], aL[4][4];
            #pragma unroll
            for (int mt = 0; mt < 4; mt++) {
                int r = wm0 + mt * 16 + (lane >> 2);
                aH[mt][0] = lds32(sw_lds(bb + SM_AHI, r,     2*ks,   lane));
                aH[mt][1] = lds32(sw_lds(bb + SM_AHI, r + 8, 2*ks,   lane));
                aH[mt][2] = lds32(sw_lds(bb + SM_AHI, r,     2*ks+1, lane));
                aH[mt][3] = lds32(sw_lds(bb + SM_AHI, r + 8, 2*ks+1, lane));
                aL[mt][0] = lds32(sw_lds(bb + SM_ALO, r,     2*ks,   lane));
                aL[mt][1] = lds32(sw_lds(bb + SM_ALO, r + 8, 2*ks,   lane));
                aL[mt][2] = lds32(sw_lds(bb + SM_ALO, r,     2*ks+1, lane));
                aL[mt][3] = lds32(sw_lds(bb + SM_ALO, r + 8, 2*ks+1, lane));
            }
            uint32_t bH[4][2], bL[4][2];
            #pragma unroll
            for (int nt = 0; nt < 4; nt++) {
                int rn = wn0 + nt * 8 + (lane >> 2);
                bH[nt][0] = lds32(sw_lds(bb + SM_BHI, rn, 2*ks,   lane));
                bH[nt][1] = lds32(sw_lds(bb + SM_BHI, rn, 2*ks+1, lane));
                bL[nt][0] = lds32(sw_lds(bb + SM_BLO, rn, 2*ks,   lane));
                bL[nt][1] = lds32(sw_lds(bb + SM_BLO, rn, 2*ks+1, lane));
            }
            #pragma unroll
            for (int mt = 0; mt < 4; mt++)
                #pragma unroll
                for (int nt = 0; nt < 4; nt++) {
                    mma_bf16(acc[mt][nt], aH[mt], bH[nt]);
                    mma_bf16(acc[mt][nt], aH[mt], bL[nt]);
                    mma_bf16(acc[mt][nt], aL[mt], bH[nt]);
                }
        }

        if (kb + 1 < 32) {
            do_sts(buf ^ 1);
            __syncthreads();
        }
    }

    // epilogue
    #pragma unroll
    for (int mt = 0; mt < 4; mt++) {
        #pragma unroll
        for (int nt = 0; nt < 4; nt++) {
            int row = m0 + wm0 + mt * 16 + (lane >> 2);
            int col = n0 + wn0 + nt * 8 + ((lane & 3) << 1);
            #pragma unroll
            for (int h = 0; h < 2; h++) {
                int r = row + h * 8;
                float2 v = make_float2(acc[mt][nt][2*h], acc[mt][nt][2*h + 1]);
                if (mode == 0) {
                    *(float2*)&C[(size_t)r * DD + col] = v;
                } else {
                    int bI = r >> 11, l = r & (LL - 1);
                    int hh = col >> 6, hd = col & 63;
                    size_t off = ((size_t)((bI * HH + hh) * LL + l) << 6) + hd;
                    if (mode == 1) {
                        *(float2*)&C[off] = v;
                    } else {
                        uint32_t vh, vl;
                        split2(v.x, v.y, vh, vl);
                        *(uint32_t*)&Ch[off] = vh;
                        *(uint32_t*)&Cl[off] = vl;
                    }
                }
            }
        }
    }
}

// ---------------------------------------------------------------------------
// Per-head LayerNorm over HD=64. mode: in-place fp32 (Q) / split bf16 out (K)
// ---------------------------------------------------------------------------
__global__ __launch_bounds__(256) void ln_head(float* __restrict__ X,
                                               const float* __restrict__ gamma,
                                               const float* __restrict__ beta)
{
    int row  = blockIdx.x * 8 + (threadIdx.x >> 5);
    int lane = threadIdx.x & 31;
    float2 v = *(float2*)&X[(size_t)row * 64 + lane * 2];
    float s  = v.x + v.y;
    float sq = v.x * v.x + v.y * v.y;
    #pragma unroll
    for (int off = 16; off > 0; off >>= 1) {
        s  += __shfl_xor_sync(0xffffffffu, s,  off);
        sq += __shfl_xor_sync(0xffffffffu, sq, off);
    }
    float mean = s * (1.0f / 64.0f);
    float var  = sq * (1.0f / 64.0f) - mean * mean;
    float inv  = rsqrtf(var + 1e-5f);
    float g0 = gamma[lane * 2],     g1 = gamma[lane * 2 + 1];
    float b0 = beta[lane * 2],      b1 = beta[lane * 2 + 1];
    v.x = (v.x - mean) * inv * g0 + b0;
    v.y = (v.y - mean) * inv * g1 + b1;
    *(float2*)&X[(size_t)row * 64 + lane * 2] = v;
}

__global__ __launch_bounds__(256) void ln_head_split(const float* __restrict__ X,
                                                     const float* __restrict__ gamma,
                                                     const float* __restrict__ beta,
                                                     __nv_bfloat16* __restrict__ Xh,
                                                     __nv_bfloat16* __restrict__ Xl)
{
    int row  = blockIdx.x * 8 + (threadIdx.x >> 5);
    int lane = threadIdx.x & 31;
    float2 v = *(const float2*)&X[(size_t)row * 64 + lane * 2];
    float s  = v.x + v.y;
    float sq = v.x * v.x + v.y * v.y;
    #pragma unroll
    for (int off = 16; off > 0; off >>= 1) {
        s  += __shfl_xor_sync(0xffffffffu, s,  off);
        sq += __shfl_xor_sync(0xffffffffu, sq, off);
    }
    float mean = s * (1.0f / 64.0f);
    float var  = sq * (1.0f / 64.0f) - mean * mean;
    float inv  = rsqrtf(var + 1e-5f);
    float g0 = gamma[lane * 2],     g1 = gamma[lane * 2 + 1];
    float b0 = beta[lane * 2],      b1 = beta[lane * 2 + 1];
    v.x = (v.x - mean) * inv * g0 + b0;
    v.y = (v.y - mean) * inv * g1 + b1;
    uint32_t h, l;
    split2(v.x, v.y, h, l);
    *(uint32_t*)&Xh[(size_t)row * 64 + lane * 2] = h;
    *(uint32_t*)&Xl[(size_t)row * 64 + lane * 2] = l;
}

// ===========================================================================
// Tensor-core causal flash attention.
// BQ=128 (8 warps x 16 rows), BK=64. bf16x3 QK^T, bf16x3 (Ph,Pl)x(Vh,Vl) PV.
// K/V tiles cp.async'd (bf16 hi/lo pre-split in gmem) into swizzled smem,
// double buffered. ldmatrix (.trans for V) fragment loads.
// smem tile: 64 rows x 128B, chunk swizzle ch ^= row&7. Buffer = 32KB x2.
// ===========================================================================
#define CS 0.18033688f   // 0.125 * log2(e)

__global__ __launch_bounds__(256, 1) void flash_mma(
    const float* __restrict__ Q,
    const __nv_bfloat16* __restrict__ Kh, const __nv_bfloat16* __restrict__ Kl,
    const __nv_bfloat16* __restrict__ Vh, const __nv_bfloat16* __restrict__ Vl,
    float* __restrict__ ctx)
{
    extern __shared__ char fsm[];
    const uint32_t smb = smem_u32(fsm);
    const int tid  = threadIdx.x;
    const int lane = tid & 31;
    const int w    = tid >> 5;
    const int bh   = blockIdx.x;
    const int qt   = (gridDim.y - 1) - blockIdx.y;   // heavy CTAs first

    const float* Qg = Q + (size_t)bh * LL * HDD;
    const __nv_bfloat16* Khg = Kh + (size_t)bh * LL * HDD;
    const __nv_bfloat16* Klg = Kl + (size_t)bh * LL * HDD;
    const __nv_bfloat16* Vhg = Vh + (size_t)bh * LL * HDD;
    const __nv_bfloat16* Vlg = Vl + (size_t)bh * LL * HDD;

    const int wq = qt * 128 + w * 16;

    // ---- Q fragments (bf16 hi/lo), 4 ksteps over HD=64 ----
    uint32_t Qah[4][4], Qal[4][4];
    {
        int ra = wq + (lane >> 2);
        #pragma unroll
        for (int ks = 0; ks < 4; ks++) {
            int d0 = ks * 16 + (lane & 3) * 2;
            float2 qa  = *(const float2*)&Qg[(size_t)ra * 64 + d0];
            float2 qb  = *(const float2*)&Qg[(size_t)(ra + 8) * 64 + d0];
            float2 qa2 = *(const float2*)&Qg[(size_t)ra * 64 + d0 + 8];
            float2 qb2 = *(const float2*)&Qg[(size_t)(ra + 8) * 64 + d0 + 8];
            split2(qa.x,  qa.y,  Qah[ks][0], Qal[ks][0]);
            split2(qb.x,  qb.y,  Qah[ks][1], Qal[ks][1]);
            split2(qa2.x, qa2.y, Qah[ks][2], Qal[ks][2]);
            split2(qb2.x, qb2.y, Qah[ks][3], Qal[ks][3]);
        }
    }

    float o[8][4] = {};
    float m0 = -1e30f, m1 = -1e30f, l0 = 0.0f, l1 = 0.0f;

    const int nkt    = 2 * (qt + 1);
    const int my_nkt = ((wq + 15) >> 6) + 1;   // warp-level skip of masked tiles

    // tile prefetch: 4 sub-tiles (Kh,Kl,Vh,Vl) x 64 rows x 8 chunks of 16B
    auto prefetch = [&](int kt, int bufb) {
        #pragma unroll
        for (int j = 0; j < 8; j++) {
            const int tile = j >> 1;                 // compile-time
            int c   = (j & 1) * 256 + tid;           // 0..511
            int row = c >> 3, ch = c & 7;
            const __nv_bfloat16* src =
                (tile == 0 ? Khg : tile == 1 ? Klg : tile == 2 ? Vhg : Vlg)
                + (size_t)(kt * 64 + row) * 64 + ch * 8;
            uint32_t dst = smb + bufb * 32768 + tile * 8192 + row * 128
                         + ((ch ^ (row & 7)) << 4);
            cp16(dst, src);
        }
    };

    prefetch(0, 0);
    CP_COMMIT();

    for (int kt = 0; kt < nkt; kt++) {
        const int buf = kt & 1;
        if (kt + 1 < nkt) prefetch(kt + 1, buf ^ 1);
        CP_COMMIT();
        CP_WAIT1();
        __syncthreads();

        if (kt < my_nkt) {
            const uint32_t bKh = smb + buf * 32768;
            const uint32_t bKl = bKh + 8192;
            const uint32_t bVh = bKh + 16384;
            const uint32_t bVl = bKh + 24576;

            // ---- S = Q K^T (bf16x3) ----
            float s[8][4] = {};
            #pragma unroll
            for (int ks = 0; ks < 4; ks++) {
                #pragma unroll
                for (int ntp = 0; ntp < 4; ntp++) {
                    int mat  = lane >> 3;
                    int key  = ntp * 16 + (mat >> 1) * 8 + (lane & 7);
                    int ch   = 2 * ks + (mat & 1);
                    uint32_t off = key * 128 + (((ch ^ (key & 7))) << 4);
                    uint32_t kh[4], kl[4];
                    ldmx4(kh, bKh + off);
                    ldmx4(kl, bKl + off);
                    mma_bf16(s[2*ntp],   Qah[ks], kh);
                    mma_bf16(s[2*ntp],   Qah[ks], kl);
                    mma_bf16(s[2*ntp],   Qal[ks], kh);
                    mma_bf16(s[2*ntp+1], Qah[ks], kh + 2);
                    mma_bf16(s[2*ntp+1], Qah[ks], kl + 2);
                    mma_bf16(s[2*ntp+1], Qal[ks], kh + 2);
                }
            }

            // ---- causal mask (only near-diagonal tiles) ----
            if ((kt << 6) + 63 > wq) {
                int q0 = wq + (lane >> 2), q1 = q0 + 8;
                #pragma unroll
                for (int nt = 0; nt < 8; nt++) {
                    int key = (kt << 6) + nt * 8 + ((lane & 3) << 1);
                    if (key     > q0) s[nt][0] = -1e30f;
                    if (key + 1 > q0) s[nt][1] = -1e30f;
                    if (key     > q1) s[nt][2] = -1e30f;
                    if (key + 1 > q1) s[nt][3] = -1e30f;
                }
            }

            // ---- online softmax (FFMA-pipe exp2) ----
            float mx0 = -1e30f, mx1 = -1e30f;
            #pragma unroll
            for (int nt = 0; nt < 8; nt++) {
                mx0 = fmaxf(mx0, fmaxf(s[nt][0], s[nt][1]));
                mx1 = fmaxf(mx1, fmaxf(s[nt][2], s[nt][3]));
            }
            mx0 = fmaxf(mx0, __shfl_xor_sync(0xffffffffu, mx0, 1));
            mx0 = fmaxf(mx0, __shfl_xor_sync(0xffffffffu, mx0, 2));
            mx1 = fmaxf(mx1, __shfl_xor_sync(0xffffffffu, mx1, 1));
            mx1 = fmaxf(mx1, __shfl_xor_sync(0xffffffffu, mx1, 2));

            float m0n = fmaxf(m0, mx0 * CS);
            float m1n = fmaxf(m1, mx1 * CS);
            float fac0 = exp2p(m0 - m0n);
            float fac1 = exp2p(m1 - m1n);

            float sum0 = 0.0f, sum1 = 0.0f;
            #pragma unroll
            for (int nt = 0; nt < 8; nt++) {
                float p0 = exp2p(fmaf(s[nt][0], CS, -m0n));
                float p1 = exp2p(fmaf(s[nt][1], CS, -m0n));
                float p2 = exp2p(fmaf(s[nt][2], CS, -m1n));
                float p3 = exp2p(fmaf(s[nt][3], CS, -m1n));
                s[nt][0] = p0; s[nt][1] = p1; s[nt][2] = p2; s[nt][3] = p3;
                sum0 += p0 + p1;
                sum1 += p2 + p3;
            }
            sum0 += __shfl_xor_sync(0xffffffffu, sum0, 1);
            sum0 += __shfl_xor_sync(0xffffffffu, sum0, 2);
            sum1 += __shfl_xor_sync(0xffffffffu, sum1, 1);
            sum1 += __shfl_xor_sync(0xffffffffu, sum1, 2);

            l0 = l0 * fac0 + sum0;  m0 = m0n;
            l1 = l1 * fac1 + sum1;  m1 = m1n;
            #pragma unroll
            for (int nt = 0; nt < 8; nt++) {
                o[nt][0] *= fac0; o[nt][1] *= fac0;
                o[nt][2] *= fac1; o[nt][3] *= fac1;
            }

            // ---- O += P V (Ph,Pl x Vh,Vl) ----
            #pragma unroll
            for (int ks = 0; ks < 4; ks++) {
                uint32_t Ph[4], Pl[4];
                split2(s[2*ks][0],   s[2*ks][1],   Ph[0], Pl[0]);
                split2(s[2*ks][2],   s[2*ks][3],   Ph[1], Pl[1]);
                split2(s[2*ks+1][0], s[2*ks+1][1], Ph[2], Pl[2]);
                split2(s[2*ks+1][2], s[2*ks+1][3], Ph[3], Pl[3]);
                #pragma unroll
                for (int ntp = 0; ntp < 4; ntp++) {
                    int mat = lane >> 3;
                    int kk  = ks * 16 + (mat & 1) * 8 + (lane & 7);
                    int ch  = ntp * 2 + (mat >> 1);
                    uint32_t off = kk * 128 + (((ch ^ (kk & 7))) << 4);
                    uint32_t vh[4], vl[4];
                    ldmx4t(vh, bVh + off);
                    ldmx4t(vl, bVl + off);
                    mma_bf16(o[2*ntp],   Ph, vh);
                    mma_bf16(o[2*ntp],   Ph, vl);
                    mma_bf16(o[2*ntp],   Pl, vh);
                    mma_bf16(o[2*ntp+1], Ph, vh + 2);
                    mma_bf16(o[2*ntp+1], Ph, vl + 2);
                    mma_bf16(o[2*ntp+1], Pl, vh + 2);
                }
            }
        }
        __syncthreads();
    }

    // ---- epilogue: normalize, write ctx [b,l,d] ----
    const int b = bh >> 4, h = bh & 15;
    const int q0 = wq + (lane >> 2), q1 = q0 + 8;
    float inv0 = 1.0f / l0, inv1 = 1.0f / l1;
    #pragma unroll
    for (int nt = 0; nt < 8; nt++) {
        int d = nt * 8 + ((lane & 3) << 1);
        *(float2*)&ctx[(size_t)(b * LL + q0) * DD + h * 64 + d] =
            make_float2(o[nt][0] * inv0, o[nt][1] * inv0);
        *(float2*)&ctx[(size_t)(b * LL + q1) * DD + h * 64 + d] =
            make_float2(o[nt][2] * inv1, o[nt][3] * inv1);
    }
}

// ---------------------------------------------------------------------------
extern "C" void kernel_launch(void* const* d_in, const int* in_sizes, int n_in,
                              void* d_out, int out_size)
{
    const float* x      = (const float*)d_in[0];
    // d_in[1] = causal mask (tril) — causality applied analytically, unused
    const float* Wq     = (const float*)d_in[2];
    const float* Wk     = (const float*)d_in[3];
    const float* Wv     = (const float*)d_in[4];
    const float* Wo     = (const float*)d_in[5];
    const float* qgamma = (const float*)d_in[6];
    const float* qbeta  = (const float*)d_in[7];
    const float* kgamma = (const float*)d_in[8];
    const float* kbeta  = (const float*)d_in[9];
    float* out = (float*)d_out;

    float *dQ, *dK, *dC;
    __nv_bfloat16 *dKh, *dKl, *dVh, *dVl;
    cudaGetSymbolAddress((void**)&dQ,  g_Q);
    cudaGetSymbolAddress((void**)&dK,  g_K);
    cudaGetSymbolAddress((void**)&dC,  g_CTX);
    cudaGetSymbolAddress((void**)&dKh, g_Kh);
    cudaGetSymbolAddress((void**)&dKl, g_Kl);
    cudaGetSymbolAddress((void**)&dVh, g_Vh);
    cudaGetSymbolAddress((void**)&dVl, g_Vl);

    const int gemm_smem = 2 * SM_BUF;   // 64 KB
    cudaFuncSetAttribute(gemm_mma,
                         cudaFuncAttributeMaxDynamicSharedMemorySize, gemm_smem);
    cudaFuncSetAttribute(flash_mma,
                         cudaFuncAttributeMaxDynamicSharedMemorySize, 65536);

    dim3 gg(DD / 128, (BB * LL) / 128);   // (8, 64)

    gemm_mma<<<gg, 256, gemm_smem>>>(x, Wq, dQ, nullptr, nullptr, 1);
    gemm_mma<<<gg, 256, gemm_smem>>>(x, Wk, dK, nullptr, nullptr, 1);
    gemm_mma<<<gg, 256, gemm_smem>>>(x, Wv, nullptr, dVh, dVl, 2);

    ln_head<<<(BB * HH * LL) / 8, 256>>>(dQ, qgamma, qbeta);
    ln_head_split<<<(BB * HH * LL) / 8, 256>>>(dK, kgamma, kbeta, dKh, dKl);

    flash_mma<<<dim3(BB * HH, LL / 128), 256, 65536>>>(dQ, dKh, dKl, dVh, dVl, dC);

    gemm_mma<<<gg, 256, gemm_smem>>>(dC, Wo, out, nullptr, nullptr, 0);
}

// round 6
// speedup vs baseline: 4.1296x; 1.1775x over previous
#include <cuda_runtime.h>
#include <cuda_bf16.h>
#include <math.h>
#include <stdint.h>

#define BB 4
#define LL 2048
#define DD 1024
#define HH 16
#define HDD 64
#define NTOK (BB*LL)            // 8192 rows
#define NEL  (BB*HH*LL*HDD)     // 8.4M elements

// Scratch (device globals — no allocations allowed)
__device__ float g_Q[NEL];      // fp32 head-major pre-LN
__device__ float g_K[NEL];
__device__ __align__(16) __nv_bfloat16 g_xh[NEL],  g_xl[NEL];     // x split
__device__ __align__(16) __nv_bfloat16 g_Wqh[DD*DD], g_Wql[DD*DD];
__device__ __align__(16) __nv_bfloat16 g_Wkh[DD*DD], g_Wkl[DD*DD];
__device__ __align__(16) __nv_bfloat16 g_Wvh[DD*DD], g_Wvl[DD*DD];
__device__ __align__(16) __nv_bfloat16 g_Woh[DD*DD], g_Wol[DD*DD];
__device__ __align__(16) __nv_bfloat16 g_Qh[NEL], g_Ql[NEL];
__device__ __align__(16) __nv_bfloat16 g_Kh[NEL], g_Kl[NEL];
__device__ __align__(16) __nv_bfloat16 g_Vh[NEL], g_Vl[NEL];
__device__ __align__(16) __nv_bfloat16 g_Ch[NEL], g_Cl[NEL];      // ctx split

// ===========================================================================
// helpers
// ===========================================================================
__device__ __forceinline__ uint32_t smem_u32(const void* p) {
    uint32_t a;
    asm("{ .reg .u64 t; cvta.to.shared.u64 t, %1; cvt.u32.u64 %0, t; }"
        : "=r"(a) : "l"(p));
    return a;
}

__device__ __forceinline__ void mma_bf16(float* c, const uint32_t* a, const uint32_t* b) {
    asm volatile(
        "mma.sync.aligned.m16n8k16.row.col.f32.bf16.bf16.f32 "
        "{%0,%1,%2,%3}, {%4,%5,%6,%7}, {%8,%9}, {%0,%1,%2,%3};"
        : "+f"(c[0]), "+f"(c[1]), "+f"(c[2]), "+f"(c[3])
        : "r"(a[0]), "r"(a[1]), "r"(a[2]), "r"(a[3]), "r"(b[0]), "r"(b[1]));
}

__device__ __forceinline__ void ldmx4(uint32_t* r, uint32_t addr) {
    asm volatile("ldmatrix.sync.aligned.m8n8.x4.shared.b16 {%0,%1,%2,%3}, [%4];"
                 : "=r"(r[0]), "=r"(r[1]), "=r"(r[2]), "=r"(r[3]) : "r"(addr));
}
__device__ __forceinline__ void ldmx4t(uint32_t* r, uint32_t addr) {
    asm volatile("ldmatrix.sync.aligned.m8n8.x4.trans.shared.b16 {%0,%1,%2,%3}, [%4];"
                 : "=r"(r[0]), "=r"(r[1]), "=r"(r[2]), "=r"(r[3]) : "r"(addr));
}

__device__ __forceinline__ void cp16(uint32_t dst, const void* src) {
    asm volatile("cp.async.cg.shared.global [%0], [%1], 16;" :: "r"(dst), "l"(src));
}
#define CP_COMMIT() asm volatile("cp.async.commit_group;" ::: "memory")
#define CP_WAIT1()  asm volatile("cp.async.wait_group 1;" ::: "memory")

// split two floats into packed bf16 hi + bf16 lo (residual)
__device__ __forceinline__ void split2(float a, float b, uint32_t& h, uint32_t& l) {
    __nv_bfloat16 ha = __float2bfloat16_rn(a);
    __nv_bfloat16 hb = __float2bfloat16_rn(b);
    float ra = a - __bfloat162float(ha);
    float rb = b - __bfloat162float(hb);
    __nv_bfloat162 hv; hv.x = ha; hv.y = hb;
    __nv_bfloat162 lv = __floats2bfloat162_rn(ra, rb);
    h = *(uint32_t*)&hv;
    l = *(uint32_t*)&lv;
}

// fast 2^t on FMA/ALU pipes (no MUFU). t <= 0 expected; clamped at -100.
__device__ __forceinline__ float exp2p(float t) {
    t = fmaxf(t, -100.0f);
    float z = t + 12582912.0f;
    float f = t - (z - 12582912.0f);
    float p =             1.3333558e-3f;
    p = fmaf(p, f, 9.6181291e-3f);
    p = fmaf(p, f, 5.5504109e-2f);
    p = fmaf(p, f, 2.4022651e-1f);
    p = fmaf(p, f, 6.9314718e-1f);
    p = fmaf(p, f, 1.0f);
    return __int_as_float(__float_as_int(p) + (__float_as_int(z) << 23));
}

// ---------------------------------------------------------------------------
// fp32 -> bf16 hi/lo splitter (vectorized, grid covers n/4 float4s)
// ---------------------------------------------------------------------------
__global__ __launch_bounds__(256) void split_f32(const float* __restrict__ X,
                                                 __nv_bfloat16* __restrict__ Xh,
                                                 __nv_bfloat16* __restrict__ Xl)
{
    int i = blockIdx.x * 256 + threadIdx.x;
    float4 v = ((const float4*)X)[i];
    uint32_t h0, l0, h1, l1;
    split2(v.x, v.y, h0, l0);
    split2(v.z, v.w, h1, l1);
    ((uint2*)Xh)[i] = make_uint2(h0, h1);
    ((uint2*)Xl)[i] = make_uint2(l0, l1);
}

// ===========================================================================
// bf16x3 GEMM on pre-split operands: C[M,1024] = A @ B^T
// A,B bf16 hi/lo row-major K-contiguous. CTA 128x128, BK=64, 8 warps (2x4).
// smem/buffer: Ah,Al,Bh,Bl tiles 128rows x 128B (16KB each) = 64KB; x2 = 128KB.
// swizzle: 16B chunk ch ^= row&7. ldmatrix fragment loads.
// mode 0: fp32 row-major; 1: fp32 head-major; 2: bf16 hi/lo head-major.
// ===========================================================================
__global__ __launch_bounds__(256) void gemm_bs(const __nv_bfloat16* __restrict__ Ah,
                                               const __nv_bfloat16* __restrict__ Al,
                                               const __nv_bfloat16* __restrict__ Bh,
                                               const __nv_bfloat16* __restrict__ Bl,
                                               float* __restrict__ C,
                                               __nv_bfloat16* __restrict__ Ch,
                                               __nv_bfloat16* __restrict__ Cl,
                                               int mode)
{
    extern __shared__ char gsm[];
    const uint32_t smb = smem_u32(gsm);
    const int tid  = threadIdx.x;
    const int lane = tid & 31;
    const int wid  = tid >> 5;
    const int wm0  = (wid & 1) * 64;
    const int wn0  = (wid >> 1) * 32;
    const int m0   = blockIdx.y * 128;
    const int n0   = blockIdx.x * 128;
    const int mat  = lane >> 3;

    float acc[4][4][4] = {};

    // prefetch k-chunk kc into buffer b: 4 tiles x 128 rows x 8 chunks of 16B
    auto prefetch = [&](int kc, int b) {
        const __nv_bfloat16* srcs[4] = { Ah, Al, Bh, Bl };
        #pragma unroll
        for (int j = 0; j < 16; j++) {
            const int tile = j >> 2;
            int c   = (j & 3) * 256 + tid;         // 0..1023
            int row = c >> 3, ch = c & 7;
            int grow = (tile < 2 ? m0 : n0) + row;
            const __nv_bfloat16* src = srcs[tile] + (size_t)grow * DD + kc * 64 + ch * 8;
            uint32_t dst = smb + b * 65536 + tile * 16384 + row * 128
                         + ((ch ^ (row & 7)) << 4);
            cp16(dst, src);
        }
    };

    prefetch(0, 0);
    CP_COMMIT();

    for (int kc = 0; kc < 16; kc++) {
        const int buf = kc & 1;
        if (kc + 1 < 16) prefetch(kc + 1, buf ^ 1);
        CP_COMMIT();
        CP_WAIT1();
        __syncthreads();

        const uint32_t bAh = smb + buf * 65536;
        const uint32_t bAl = bAh + 16384;
        const uint32_t bBh = bAh + 32768;
        const uint32_t bBl = bAh + 49152;

        #pragma unroll
        for (int ks = 0; ks < 4; ks++) {
            uint32_t aH[4][4], aL[4][4];
            #pragma unroll
            for (int mt = 0; mt < 4; mt++) {
                int r  = wm0 + mt * 16 + ((mat & 1) << 3) + (lane & 7);
                int ch = 2 * ks + (mat >> 1);
                uint32_t off = r * 128 + ((ch ^ (r & 7)) << 4);
                ldmx4(aH[mt], bAh + off);
                ldmx4(aL[mt], bAl + off);
            }
            uint32_t bH[2][4], bL[2][4];
            #pragma unroll
            for (int np = 0; np < 2; np++) {
                int rn = wn0 + np * 16 + ((mat >> 1) << 3) + (lane & 7);
                int ch = 2 * ks + (mat & 1);
                uint32_t off = rn * 128 + ((ch ^ (rn & 7)) << 4);
                ldmx4(bH[np], bBh + off);
                ldmx4(bL[np], bBl + off);
            }
            #pragma unroll
            for (int mt = 0; mt < 4; mt++)
                #pragma unroll
                for (int np = 0; np < 2; np++) {
                    mma_bf16(acc[mt][2*np],   aH[mt], bH[np]);
                    mma_bf16(acc[mt][2*np],   aH[mt], bL[np]);
                    mma_bf16(acc[mt][2*np],   aL[mt], bH[np]);
                    mma_bf16(acc[mt][2*np+1], aH[mt], bH[np] + 2);
                    mma_bf16(acc[mt][2*np+1], aH[mt], bL[np] + 2);
                    mma_bf16(acc[mt][2*np+1], aL[mt], bH[np] + 2);
                }
        }
        __syncthreads();
    }

    // epilogue
    #pragma unroll
    for (int mt = 0; mt < 4; mt++) {
        #pragma unroll
        for (int nt = 0; nt < 4; nt++) {
            int row = m0 + wm0 + mt * 16 + (lane >> 2);
            int col = n0 + wn0 + nt * 8 + ((lane & 3) << 1);
            #pragma unroll
            for (int hf = 0; hf < 2; hf++) {
                int r = row + hf * 8;
                float2 v = make_float2(acc[mt][nt][2*hf], acc[mt][nt][2*hf + 1]);
                if (mode == 0) {
                    *(float2*)&C[(size_t)r * DD + col] = v;
                } else {
                    int bI = r >> 11, l = r & (LL - 1);
                    int hh = col >> 6, hd = col & 63;
                    size_t off = ((size_t)((bI * HH + hh) * LL + l) << 6) + hd;
                    if (mode == 1) {
                        *(float2*)&C[off] = v;
                    } else {
                        uint32_t vh, vl;
                        split2(v.x, v.y, vh, vl);
                        *(uint32_t*)&Ch[off] = vh;
                        *(uint32_t*)&Cl[off] = vl;
                    }
                }
            }
        }
    }
}

// ---------------------------------------------------------------------------
// Per-head LayerNorm over HD=64, fp32 in -> bf16 hi/lo out.
// ---------------------------------------------------------------------------
__global__ __launch_bounds__(256) void ln_head_split(const float* __restrict__ X,
                                                     const float* __restrict__ gamma,
                                                     const float* __restrict__ beta,
                                                     __nv_bfloat16* __restrict__ Xh,
                                                     __nv_bfloat16* __restrict__ Xl)
{
    int row  = blockIdx.x * 8 + (threadIdx.x >> 5);
    int lane = threadIdx.x & 31;
    float2 v = *(const float2*)&X[(size_t)row * 64 + lane * 2];
    float s  = v.x + v.y;
    float sq = v.x * v.x + v.y * v.y;
    #pragma unroll
    for (int off = 16; off > 0; off >>= 1) {
        s  += __shfl_xor_sync(0xffffffffu, s,  off);
        sq += __shfl_xor_sync(0xffffffffu, sq, off);
    }
    float mean = s * (1.0f / 64.0f);
    float var  = sq * (1.0f / 64.0f) - mean * mean;
    float inv  = rsqrtf(var + 1e-5f);
    float g0 = gamma[lane * 2],     g1 = gamma[lane * 2 + 1];
    float b0 = beta[lane * 2],      b1 = beta[lane * 2 + 1];
    v.x = (v.x - mean) * inv * g0 + b0;
    v.y = (v.y - mean) * inv * g1 + b1;
    uint32_t h, l;
    split2(v.x, v.y, h, l);
    *(uint32_t*)&Xh[(size_t)row * 64 + lane * 2] = h;
    *(uint32_t*)&Xl[(size_t)row * 64 + lane * 2] = l;
}

// ===========================================================================
// Tensor-core causal flash attention (pre-split bf16 Q/K/V).
// BQ=128 (8 warps x 16 rows), BK=64. Epilogue writes bf16 hi/lo ctx.
// ===========================================================================
#define CS 0.18033688f   // 0.125 * log2(e)

__global__ __launch_bounds__(256, 1) void flash_mma(
    const __nv_bfloat16* __restrict__ Qh, const __nv_bfloat16* __restrict__ Ql,
    const __nv_bfloat16* __restrict__ Kh, const __nv_bfloat16* __restrict__ Kl,
    const __nv_bfloat16* __restrict__ Vh, const __nv_bfloat16* __restrict__ Vl,
    __nv_bfloat16* __restrict__ ctxh, __nv_bfloat16* __restrict__ ctxl)
{
    extern __shared__ char fsm[];
    const uint32_t smb = smem_u32(fsm);
    const int tid  = threadIdx.x;
    const int lane = tid & 31;
    const int w    = tid >> 5;
    const int bh   = blockIdx.x;
    const int qt   = (gridDim.y - 1) - blockIdx.y;   // heavy CTAs first

    const __nv_bfloat16* Qhg = Qh + (size_t)bh * LL * HDD;
    const __nv_bfloat16* Qlg = Ql + (size_t)bh * LL * HDD;
    const __nv_bfloat16* Khg = Kh + (size_t)bh * LL * HDD;
    const __nv_bfloat16* Klg = Kl + (size_t)bh * LL * HDD;
    const __nv_bfloat16* Vhg = Vh + (size_t)bh * LL * HDD;
    const __nv_bfloat16* Vlg = Vl + (size_t)bh * LL * HDD;

    const int wq = qt * 128 + w * 16;

    // ---- Q fragments (bf16 hi/lo) loaded directly ----
    uint32_t Qah[4][4], Qal[4][4];
    {
        int ra = wq + (lane >> 2);
        #pragma unroll
        for (int ks = 0; ks < 4; ks++) {
            int d0 = ks * 16 + (lane & 3) * 2;
            Qah[ks][0] = *(const uint32_t*)&Qhg[(size_t)ra * 64 + d0];
            Qah[ks][1] = *(const uint32_t*)&Qhg[(size_t)(ra + 8) * 64 + d0];
            Qah[ks][2] = *(const uint32_t*)&Qhg[(size_t)ra * 64 + d0 + 8];
            Qah[ks][3] = *(const uint32_t*)&Qhg[(size_t)(ra + 8) * 64 + d0 + 8];
            Qal[ks][0] = *(const uint32_t*)&Qlg[(size_t)ra * 64 + d0];
            Qal[ks][1] = *(const uint32_t*)&Qlg[(size_t)(ra + 8) * 64 + d0];
            Qal[ks][2] = *(const uint32_t*)&Qlg[(size_t)ra * 64 + d0 + 8];
            Qal[ks][3] = *(const uint32_t*)&Qlg[(size_t)(ra + 8) * 64 + d0 + 8];
        }
    }

    float o[8][4] = {};
    float m0 = -1e30f, m1 = -1e30f, l0 = 0.0f, l1 = 0.0f;

    const int nkt    = 2 * (qt + 1);
    const int my_nkt = ((wq + 15) >> 6) + 1;

    auto prefetch = [&](int kt, int bufb) {
        #pragma unroll
        for (int j = 0; j < 8; j++) {
            const int tile = j >> 1;
            int c   = (j & 1) * 256 + tid;
            int row = c >> 3, ch = c & 7;
            const __nv_bfloat16* src =
                (tile == 0 ? Khg : tile == 1 ? Klg : tile == 2 ? Vhg : Vlg)
                + (size_t)(kt * 64 + row) * 64 + ch * 8;
            uint32_t dst = smb + bufb * 32768 + tile * 8192 + row * 128
                         + ((ch ^ (row & 7)) << 4);
            cp16(dst, src);
        }
    };

    prefetch(0, 0);
    CP_COMMIT();

    for (int kt = 0; kt < nkt; kt++) {
        const int buf = kt & 1;
        if (kt + 1 < nkt) prefetch(kt + 1, buf ^ 1);
        CP_COMMIT();
        CP_WAIT1();
        __syncthreads();

        if (kt < my_nkt) {
            const uint32_t bKh = smb + buf * 32768;
            const uint32_t bKl = bKh + 8192;
            const uint32_t bVh = bKh + 16384;
            const uint32_t bVl = bKh + 24576;

            float s[8][4] = {};
            #pragma unroll
            for (int ks = 0; ks < 4; ks++) {
                #pragma unroll
                for (int ntp = 0; ntp < 4; ntp++) {
                    int mat  = lane >> 3;
                    int key  = ntp * 16 + (mat >> 1) * 8 + (lane & 7);
                    int ch   = 2 * ks + (mat & 1);
                    uint32_t off = key * 128 + (((ch ^ (key & 7))) << 4);
                    uint32_t kh[4], kl[4];
                    ldmx4(kh, bKh + off);
                    ldmx4(kl, bKl + off);
                    mma_bf16(s[2*ntp],   Qah[ks], kh);
                    mma_bf16(s[2*ntp],   Qah[ks], kl);
                    mma_bf16(s[2*ntp],   Qal[ks], kh);
                    mma_bf16(s[2*ntp+1], Qah[ks], kh + 2);
                    mma_bf16(s[2*ntp+1], Qah[ks], kl + 2);
                    mma_bf16(s[2*ntp+1], Qal[ks], kh + 2);
                }
            }

            if ((kt << 6) + 63 > wq) {
                int q0 = wq + (lane >> 2), q1 = q0 + 8;
                #pragma unroll
                for (int nt = 0; nt < 8; nt++) {
                    int key = (kt << 6) + nt * 8 + ((lane & 3) << 1);
                    if (key     > q0) s[nt][0] = -1e30f;
                    if (key + 1 > q0) s[nt][1] = -1e30f;
                    if (key     > q1) s[nt][2] = -1e30f;
                    if (key + 1 > q1) s[nt][3] = -1e30f;
                }
            }

            float mx0 = -1e30f, mx1 = -1e30f;
            #pragma unroll
            for (int nt = 0; nt < 8; nt++) {
                mx0 = fmaxf(mx0, fmaxf(s[nt][0], s[nt][1]));
                mx1 = fmaxf(mx1, fmaxf(s[nt][2], s[nt][3]));
            }
            mx0 = fmaxf(mx0, __shfl_xor_sync(0xffffffffu, mx0, 1));
            mx0 = fmaxf(mx0, __shfl_xor_sync(0xffffffffu, mx0, 2));
            mx1 = fmaxf(mx1, __shfl_xor_sync(0xffffffffu, mx1, 1));
            mx1 = fmaxf(mx1, __shfl_xor_sync(0xffffffffu, mx1, 2));

            float m0n = fmaxf(m0, mx0 * CS);
            float m1n = fmaxf(m1, mx1 * CS);
            float fac0 = exp2p(m0 - m0n);
            float fac1 = exp2p(m1 - m1n);

            float sum0 = 0.0f, sum1 = 0.0f;
            #pragma unroll
            for (int nt = 0; nt < 8; nt++) {
                float p0 = exp2p(fmaf(s[nt][0], CS, -m0n));
                float p1 = exp2p(fmaf(s[nt][1], CS, -m0n));
                float p2 = exp2p(fmaf(s[nt][2], CS, -m1n));
                float p3 = exp2p(fmaf(s[nt][3], CS, -m1n));
                s[nt][0] = p0; s[nt][1] = p1; s[nt][2] = p2; s[nt][3] = p3;
                sum0 += p0 + p1;
                sum1 += p2 + p3;
            }
            sum0 += __shfl_xor_sync(0xffffffffu, sum0, 1);
            sum0 += __shfl_xor_sync(0xffffffffu, sum0, 2);
            sum1 += __shfl_xor_sync(0xffffffffu, sum1, 1);
            sum1 += __shfl_xor_sync(0xffffffffu, sum1, 2);

            l0 = l0 * fac0 + sum0;  m0 = m0n;
            l1 = l1 * fac1 + sum1;  m1 = m1n;
            #pragma unroll
            for (int nt = 0; nt < 8; nt++) {
                o[nt][0] *= fac0; o[nt][1] *= fac0;
                o[nt][2] *= fac1; o[nt][3] *= fac1;
            }

            #pragma unroll
            for (int ks = 0; ks < 4; ks++) {
                uint32_t Ph[4], Pl[4];
                split2(s[2*ks][0],   s[2*ks][1],   Ph[0], Pl[0]);
                split2(s[2*ks][2],   s[2*ks][3],   Ph[1], Pl[1]);
                split2(s[2*ks+1][0], s[2*ks+1][1], Ph[2], Pl[2]);
                split2(s[2*ks+1][2], s[2*ks+1][3], Ph[3], Pl[3]);
                #pragma unroll
                for (int ntp = 0; ntp < 4; ntp++) {
                    int mat = lane >> 3;
                    int kk  = ks * 16 + (mat & 1) * 8 + (lane & 7);
                    int ch  = ntp * 2 + (mat >> 1);
                    uint32_t off = kk * 128 + (((ch ^ (kk & 7))) << 4);
                    uint32_t vh[4], vl[4];
                    ldmx4t(vh, bVh + off);
                    ldmx4t(vl, bVl + off);
                    mma_bf16(o[2*ntp],   Ph, vh);
                    mma_bf16(o[2*ntp],   Ph, vl);
                    mma_bf16(o[2*ntp],   Pl, vh);
                    mma_bf16(o[2*ntp+1], Ph, vh + 2);
                    mma_bf16(o[2*ntp+1], Ph, vl + 2);
                    mma_bf16(o[2*ntp+1], Pl, vh + 2);
                }
            }
        }
        __syncthreads();
    }

    // ---- epilogue: normalize, split, write ctx hi/lo [b,l,d] ----
    const int b = bh >> 4, hdh = bh & 15;
    const int q0 = wq + (lane >> 2), q1 = q0 + 8;
    float inv0 = 1.0f / l0, inv1 = 1.0f / l1;
    #pragma unroll
    for (int nt = 0; nt < 8; nt++) {
        int d = nt * 8 + ((lane & 3) << 1);
        size_t o0 = (size_t)(b * LL + q0) * DD + hdh * 64 + d;
        size_t o1 = (size_t)(b * LL + q1) * DD + hdh * 64 + d;
        uint32_t vh, vl;
        split2(o[nt][0] * inv0, o[nt][1] * inv0, vh, vl);
        *(uint32_t*)&ctxh[o0] = vh;
        *(uint32_t*)&ctxl[o0] = vl;
        split2(o[nt][2] * inv1, o[nt][3] * inv1, vh, vl);
        *(uint32_t*)&ctxh[o1] = vh;
        *(uint32_t*)&ctxl[o1] = vl;
    }
}

// ---------------------------------------------------------------------------
extern "C" void kernel_launch(void* const* d_in, const int* in_sizes, int n_in,
                              void* d_out, int out_size)
{
    const float* x      = (const float*)d_in[0];
    // d_in[1] = causal mask (tril) — causality applied analytically, unused
    const float* Wq     = (const float*)d_in[2];
    const float* Wk     = (const float*)d_in[3];
    const float* Wv     = (const float*)d_in[4];
    const float* Wo     = (const float*)d_in[5];
    const float* qgamma = (const float*)d_in[6];
    const float* qbeta  = (const float*)d_in[7];
    const float* kgamma = (const float*)d_in[8];
    const float* kbeta  = (const float*)d_in[9];
    float* out = (float*)d_out;

    float *dQ, *dK;
    __nv_bfloat16 *dxh, *dxl, *dQh, *dQl, *dKh, *dKl, *dVh, *dVl, *dCh, *dCl;
    __nv_bfloat16 *dWqh, *dWql, *dWkh, *dWkl, *dWvh, *dWvl, *dWoh, *dWol;
    cudaGetSymbolAddress((void**)&dQ,  g_Q);
    cudaGetSymbolAddress((void**)&dK,  g_K);
    cudaGetSymbolAddress((void**)&dxh, g_xh);   cudaGetSymbolAddress((void**)&dxl, g_xl);
    cudaGetSymbolAddress((void**)&dQh, g_Qh);   cudaGetSymbolAddress((void**)&dQl, g_Ql);
    cudaGetSymbolAddress((void**)&dKh, g_Kh);   cudaGetSymbolAddress((void**)&dKl, g_Kl);
    cudaGetSymbolAddress((void**)&dVh, g_Vh);   cudaGetSymbolAddress((void**)&dVl, g_Vl);
    cudaGetSymbolAddress((void**)&dCh, g_Ch);   cudaGetSymbolAddress((void**)&dCl, g_Cl);
    cudaGetSymbolAddress((void**)&dWqh, g_Wqh); cudaGetSymbolAddress((void**)&dWql, g_Wql);
    cudaGetSymbolAddress((void**)&dWkh, g_Wkh); cudaGetSymbolAddress((void**)&dWkl, g_Wkl);
    cudaGetSymbolAddress((void**)&dWvh, g_Wvh); cudaGetSymbolAddress((void**)&dWvl, g_Wvl);
    cudaGetSymbolAddress((void**)&dWoh, g_Woh); cudaGetSymbolAddress((void**)&dWol, g_Wol);

    const int gemm_smem = 131072;
    cudaFuncSetAttribute(gemm_bs,
                         cudaFuncAttributeMaxDynamicSharedMemorySize, gemm_smem);
    cudaFuncSetAttribute(flash_mma,
                         cudaFuncAttributeMaxDynamicSharedMemorySize, 65536);

    // operand pre-splits
    split_f32<<<NEL / 1024, 256>>>(x,  dxh, dxl);
    split_f32<<<DD * DD / 1024, 256>>>(Wq, dWqh, dWql);
    split_f32<<<DD * DD / 1024, 256>>>(Wk, dWkh, dWkl);
    split_f32<<<DD * DD / 1024, 256>>>(Wv, dWvh, dWvl);
    split_f32<<<DD * DD / 1024, 256>>>(Wo, dWoh, dWol);

    dim3 gg(DD / 128, NTOK / 128);   // (8, 64)

    gemm_bs<<<gg, 256, gemm_smem>>>(dxh, dxl, dWqh, dWql, dQ, nullptr, nullptr, 1);
    gemm_bs<<<gg, 256, gemm_smem>>>(dxh, dxl, dWkh, dWkl, dK, nullptr, nullptr, 1);
    gemm_bs<<<gg, 256, gemm_smem>>>(dxh, dxl, dWvh, dWvl, nullptr, dVh, dVl, 2);

    ln_head_split<<<(BB * HH * LL) / 8, 256>>>(dQ, qgamma, qbeta, dQh, dQl);
    ln_head_split<<<(BB * HH * LL) / 8, 256>>>(dK, kgamma, kbeta, dKh, dKl);

    flash_mma<<<dim3(BB * HH, LL / 128), 256, 65536>>>(dQh, dQl, dKh, dKl,
                                                       dVh, dVl, dCh, dCl);

    gemm_bs<<<gg, 256, gemm_smem>>>(dCh, dCl, dWoh, dWol, out, nullptr, nullptr, 0);
}